// round 1
// baseline (speedup 1.0000x reference)
#include <cuda_runtime.h>
#include <math.h>

#define Bb 2
#define Tt 2048
#define Dd 1024
#define Hh 16
#define HDd 64
#define NEe 17

// Scratch (static device globals — allowed; runtime alloc is not)
__device__ float g_q[Bb*Hh*Tt*HDd];
__device__ float g_k[Bb*Hh*Tt*HDd];
__device__ float g_v[Bb*Hh*Tt*HDd];
__device__ float g_ao[Bb*Tt*Dd];

// ---------------------------------------------------------------------------
// QKV GEMM: C[4096,3072] = x[4096,1024] @ Wqkv[1024,3072]
// Epilogue scatters into g_q/g_k/g_v with [b,h,t,d] layout.
// 64x64 tile, BK=16, 256 threads, 4x4 register blocking.
// ---------------------------------------------------------------------------
__global__ __launch_bounds__(256) void qkv_gemm(const float* __restrict__ x,
                                                const float* __restrict__ W) {
    const int K = Dd, N = 3 * Dd;
    __shared__ float Ast[16][68];   // A transposed: Ast[k][m]
    __shared__ float Bs[16][64];

    int tid = threadIdx.x;
    int tx = tid % 16, ty = tid / 16;
    int m0 = blockIdx.y * 64, n0 = blockIdx.x * 64;

    float acc[4][4] = {};

    for (int k0 = 0; k0 < K; k0 += 16) {
        {   // A tile 64x16 -> transposed
            int r = tid / 4, c4 = (tid % 4) * 4;
            float4 a = *(const float4*)&x[(m0 + r) * K + k0 + c4];
            Ast[c4 + 0][r] = a.x; Ast[c4 + 1][r] = a.y;
            Ast[c4 + 2][r] = a.z; Ast[c4 + 3][r] = a.w;
        }
        {   // B tile 16x64
            int r = tid / 16, c4 = (tid % 16) * 4;
            *(float4*)&Bs[r][c4] = *(const float4*)&W[(k0 + r) * N + n0 + c4];
        }
        __syncthreads();
#pragma unroll
        for (int k = 0; k < 16; k++) {
            float4 ra = *(float4*)&Ast[k][ty * 4];
            float4 rb = *(float4*)&Bs[k][tx * 4];
            float av[4] = {ra.x, ra.y, ra.z, ra.w};
            float bv[4] = {rb.x, rb.y, rb.z, rb.w};
#pragma unroll
            for (int i = 0; i < 4; i++)
#pragma unroll
                for (int j = 0; j < 4; j++) acc[i][j] += av[i] * bv[j];
        }
        __syncthreads();
    }

#pragma unroll
    for (int i = 0; i < 4; i++) {
        int m = m0 + ty * 4 + i;
        int b = m / Tt, t = m % Tt;
#pragma unroll
        for (int j = 0; j < 4; j++) {
            int n = n0 + tx * 4 + j;
            int which = n / Dd;
            int h = (n % Dd) / HDd;
            int d = n % HDd;
            float* dst = (which == 0) ? g_q : ((which == 1) ? g_k : g_v);
            dst[((b * Hh + h) * Tt + t) * HDd + d] = acc[i][j];
        }
    }
}

// ---------------------------------------------------------------------------
// Proj GEMM: out[4096,1024] = g_ao[4096,1024] @ Wproj[1024,1024]
// ---------------------------------------------------------------------------
__global__ __launch_bounds__(256) void proj_gemm(const float* __restrict__ W,
                                                 float* __restrict__ out) {
    const int K = Dd, N = Dd;
    __shared__ float Ast[16][68];
    __shared__ float Bs[16][64];

    int tid = threadIdx.x;
    int tx = tid % 16, ty = tid / 16;
    int m0 = blockIdx.y * 64, n0 = blockIdx.x * 64;

    float acc[4][4] = {};

    for (int k0 = 0; k0 < K; k0 += 16) {
        {
            int r = tid / 4, c4 = (tid % 4) * 4;
            float4 a = *(const float4*)&g_ao[(m0 + r) * K + k0 + c4];
            Ast[c4 + 0][r] = a.x; Ast[c4 + 1][r] = a.y;
            Ast[c4 + 2][r] = a.z; Ast[c4 + 3][r] = a.w;
        }
        {
            int r = tid / 16, c4 = (tid % 16) * 4;
            *(float4*)&Bs[r][c4] = *(const float4*)&W[(k0 + r) * N + n0 + c4];
        }
        __syncthreads();
#pragma unroll
        for (int k = 0; k < 16; k++) {
            float4 ra = *(float4*)&Ast[k][ty * 4];
            float4 rb = *(float4*)&Bs[k][tx * 4];
            float av[4] = {ra.x, ra.y, ra.z, ra.w};
            float bv[4] = {rb.x, rb.y, rb.z, rb.w};
#pragma unroll
            for (int i = 0; i < 4; i++)
#pragma unroll
                for (int j = 0; j < 4; j++) acc[i][j] += av[i] * bv[j];
        }
        __syncthreads();
    }

#pragma unroll
    for (int i = 0; i < 4; i++) {
        int m = m0 + ty * 4 + i;
#pragma unroll
        for (int j = 0; j < 4; j += 4) {
            float4 o = make_float4(acc[i][0], acc[i][1], acc[i][2], acc[i][3]);
            *(float4*)&out[m * N + n0 + tx * 4] = o;
        }
    }
}

// ---------------------------------------------------------------------------
// Flash attention with graph/edge bias + causal mask.
// Block = (b, h, 64-row q-tile). 256 threads = 16x16, 4x4 register blocking.
// ---------------------------------------------------------------------------
__global__ __launch_bounds__(256) void attn_kernel(
    const float* __restrict__ graph_adj, const int* __restrict__ edge_types,
    const float* __restrict__ adj_bias, const float* __restrict__ edge_table) {

    extern __shared__ float sm[];
    float* Qs  = sm;                // [64][68] (pre-scaled)
    float* Kt  = Qs + 64 * 68;      // [d][kk]  [64][68]
    float* Vs  = Kt + 64 * 68;      // [kk][d]  [64][68]
    float* Ss  = Vs + 64 * 68;      // [q][kk]  [64][68], becomes P in place
    float* m_s = Ss + 64 * 68;      // [64]
    float* l_s = m_s + 64;          // [64]
    float* a_s = l_s + 64;          // [64] alpha
    float* et  = a_s + 64;          // [NE*H]

    int tid = threadIdx.x;
    int tx = tid % 16, ty = tid / 16;
    int lane = tid & 31, w = tid >> 5;

    int qt = blockIdx.x, h = blockIdx.y, b = blockIdx.z;
    int q0 = qt * 64;
    const float scale = 0.125f;     // 1/sqrt(64)
    float bias_h = adj_bias[h];

    for (int i = tid; i < NEe * Hh; i += 256) et[i] = edge_table[i];

    {   // Q tile, pre-scaled
        const float* qb = &g_q[((b * Hh + h) * Tt + q0) * HDd];
        for (int i = tid; i < 64 * 16; i += 256) {
            int r = i / 16, c4 = (i % 16) * 4;
            float4 v = *(const float4*)&qb[r * 64 + c4];
            Qs[r * 68 + c4 + 0] = v.x * scale;
            Qs[r * 68 + c4 + 1] = v.y * scale;
            Qs[r * 68 + c4 + 2] = v.z * scale;
            Qs[r * 68 + c4 + 3] = v.w * scale;
        }
    }
    if (tid < 64) { m_s[tid] = -1e30f; l_s[tid] = 0.f; }

    float O[4][4] = {};
    __syncthreads();

    for (int jt = 0; jt <= qt; jt++) {
        int k0 = jt * 64;
        const float* kb = &g_k[((b * Hh + h) * Tt + k0) * HDd];
        const float* vb = &g_v[((b * Hh + h) * Tt + k0) * HDd];
        for (int i = tid; i < 64 * 16; i += 256) {
            int r = i / 16, c4 = (i % 16) * 4;
            float4 kv = *(const float4*)&kb[r * 64 + c4];
            Kt[(c4 + 0) * 68 + r] = kv.x;
            Kt[(c4 + 1) * 68 + r] = kv.y;
            Kt[(c4 + 2) * 68 + r] = kv.z;
            Kt[(c4 + 3) * 68 + r] = kv.w;
            *(float4*)&Vs[r * 68 + c4] = *(const float4*)&vb[r * 64 + c4];
        }
        __syncthreads();

        // S = Q @ K^T (scaled Q)
        float s[4][4] = {};
#pragma unroll 8
        for (int d = 0; d < 64; d++) {
            float a0 = Qs[(ty * 4 + 0) * 68 + d];
            float a1 = Qs[(ty * 4 + 1) * 68 + d];
            float a2 = Qs[(ty * 4 + 2) * 68 + d];
            float a3 = Qs[(ty * 4 + 3) * 68 + d];
            float4 kr = *(float4*)&Kt[d * 68 + tx * 4];
            float bv[4] = {kr.x, kr.y, kr.z, kr.w};
#pragma unroll
            for (int j = 0; j < 4; j++) {
                s[0][j] += a0 * bv[j];
                s[1][j] += a1 * bv[j];
                s[2][j] += a2 * bv[j];
                s[3][j] += a3 * bv[j];
            }
        }

        // bias + causal mask, write to Ss
        int qg0 = q0 + ty * 4;
        int kg0 = k0 + tx * 4;
#pragma unroll
        for (int i = 0; i < 4; i++) {
            int qg = qg0 + i;
            const float* gar = &graph_adj[(b * Tt + qg) * Tt + kg0];
            const int*   etr = &edge_types[(b * Tt + qg) * Tt + kg0];
            float4 ga = *(const float4*)gar;
            int4  ev  = *(const int4*)etr;
            float sv[4];
            sv[0] = s[i][0] + bias_h * ga.x + et[ev.x * Hh + h];
            sv[1] = s[i][1] + bias_h * ga.y + et[ev.y * Hh + h];
            sv[2] = s[i][2] + bias_h * ga.z + et[ev.z * Hh + h];
            sv[3] = s[i][3] + bias_h * ga.w + et[ev.w * Hh + h];
#pragma unroll
            for (int j = 0; j < 4; j++)
                if (kg0 + j > qg) sv[j] = -1e30f;
            *(float4*)&Ss[(ty * 4 + i) * 68 + tx * 4] =
                make_float4(sv[0], sv[1], sv[2], sv[3]);
        }
        __syncthreads();

        // online softmax: warp w owns rows w*8..w*8+7
        for (int rr = 0; rr < 8; rr++) {
            int r = w * 8 + rr;
            float v0 = Ss[r * 68 + lane];
            float v1 = Ss[r * 68 + lane + 32];
            float mx = fmaxf(v0, v1);
#pragma unroll
            for (int o = 16; o; o >>= 1)
                mx = fmaxf(mx, __shfl_xor_sync(0xffffffffu, mx, o));
            float mprev = m_s[r];
            float mnew = fmaxf(mprev, mx);
            float p0 = __expf(v0 - mnew);
            float p1 = __expf(v1 - mnew);
            Ss[r * 68 + lane] = p0;
            Ss[r * 68 + lane + 32] = p1;
            float sum = p0 + p1;
#pragma unroll
            for (int o = 16; o; o >>= 1)
                sum += __shfl_xor_sync(0xffffffffu, sum, o);
            if (lane == 0) {
                float alpha = expf(mprev - mnew);
                m_s[r] = mnew;
                l_s[r] = l_s[r] * alpha + sum;
                a_s[r] = alpha;
            }
        }
        __syncthreads();

        // O = O*alpha + P @ V
        float al[4];
#pragma unroll
        for (int i = 0; i < 4; i++) al[i] = a_s[ty * 4 + i];
#pragma unroll
        for (int i = 0; i < 4; i++)
#pragma unroll
            for (int j = 0; j < 4; j++) O[i][j] *= al[i];

#pragma unroll 8
        for (int kk = 0; kk < 64; kk++) {
            float a0 = Ss[(ty * 4 + 0) * 68 + kk];
            float a1 = Ss[(ty * 4 + 1) * 68 + kk];
            float a2 = Ss[(ty * 4 + 2) * 68 + kk];
            float a3 = Ss[(ty * 4 + 3) * 68 + kk];
            float4 vr = *(float4*)&Vs[kk * 68 + tx * 4];
            float bv[4] = {vr.x, vr.y, vr.z, vr.w};
#pragma unroll
            for (int j = 0; j < 4; j++) {
                O[0][j] += a0 * bv[j];
                O[1][j] += a1 * bv[j];
                O[2][j] += a2 * bv[j];
                O[3][j] += a3 * bv[j];
            }
        }
        __syncthreads();
    }

    // finalize: divide by l, store [b,t, h*64+d]
#pragma unroll
    for (int i = 0; i < 4; i++) {
        int r = ty * 4 + i;
        float inv = 1.0f / l_s[r];
        int qg = q0 + r;
        float4 o = make_float4(O[i][0] * inv, O[i][1] * inv,
                               O[i][2] * inv, O[i][3] * inv);
        *(float4*)&g_ao[(b * Tt + qg) * Dd + h * HDd + tx * 4] = o;
    }
}

// ---------------------------------------------------------------------------
extern "C" void kernel_launch(void* const* d_in, const int* in_sizes, int n_in,
                              void* d_out, int out_size) {
    const float* x     = (const float*)d_in[0];
    const float* gadj  = (const float*)d_in[1];
    const int*   etyp  = (const int*)d_in[2];
    const float* wqkv  = (const float*)d_in[3];
    const float* wproj = (const float*)d_in[4];
    const float* abias = (const float*)d_in[5];
    const float* etab  = (const float*)d_in[6];
    float* out = (float*)d_out;

    qkv_gemm<<<dim3(48, 64), 256>>>(x, wqkv);

    size_t shm = (size_t)(4 * 64 * 68 + 3 * 64 + NEe * Hh) * sizeof(float);
    cudaFuncSetAttribute(attn_kernel,
                         cudaFuncAttributeMaxDynamicSharedMemorySize, (int)shm);
    attn_kernel<<<dim3(Tt / 64, Hh, Bb), 256, shm>>>(gadj, etyp, abias, etab);

    proj_gemm<<<dim3(16, 64), 256>>>(wproj, out);
}

// round 3
// speedup vs baseline: 1.4874x; 1.4874x over previous
#include <cuda_runtime.h>
#include <cuda_bf16.h>
#include <math.h>
#include <cstdint>

#define Bb 2
#define Tt 2048
#define Dd 1024
#define Hh 16
#define HDd 64
#define NEe 17
#define GK 1024

// ---------------- scratch globals ----------------
__device__ float g_q[Bb*Hh*Tt*HDd];
__device__ float g_k[Bb*Hh*Tt*HDd];
__device__ float g_v[Bb*Hh*Tt*HDd];
__device__ float g_ao[Bb*Tt*Dd];

__device__ __nv_bfloat16 g_xhi[Bb*Tt*Dd],  g_xlo[Bb*Tt*Dd];
__device__ __nv_bfloat16 g_wqThi[3*Dd*Dd], g_wqTlo[3*Dd*Dd];   // Wqkv^T [3072,1024]
__device__ __nv_bfloat16 g_wpThi[Dd*Dd],   g_wpTlo[Dd*Dd];     // Wproj^T [1024,1024]
__device__ __nv_bfloat16 g_aohi[Bb*Tt*Dd], g_aolo[Bb*Tt*Dd];

// ---------------- helpers ----------------
__device__ __forceinline__ uint32_t smem_u32(const void* p) {
    uint32_t a;
    asm("{ .reg .u64 t; cvta.to.shared.u64 t, %1; cvt.u32.u64 %0, t; }" : "=r"(a) : "l"(p));
    return a;
}

__device__ __forceinline__ void ldsm4(uint32_t* r, uint32_t addr) {
    asm volatile("ldmatrix.sync.aligned.m8n8.x4.shared.b16 {%0,%1,%2,%3}, [%4];"
        : "=r"(r[0]), "=r"(r[1]), "=r"(r[2]), "=r"(r[3]) : "r"(addr));
}

__device__ __forceinline__ void mma16816(float* c, const uint32_t* a, const uint32_t* b) {
    asm volatile("mma.sync.aligned.m16n8k16.row.col.f32.bf16.bf16.f32 "
        "{%0,%1,%2,%3}, {%4,%5,%6,%7}, {%8,%9}, {%0,%1,%2,%3};"
        : "+f"(c[0]), "+f"(c[1]), "+f"(c[2]), "+f"(c[3])
        : "r"(a[0]), "r"(a[1]), "r"(a[2]), "r"(a[3]), "r"(b[0]), "r"(b[1]));
}

// ---------------- prep kernels ----------------
__global__ __launch_bounds__(256) void split_kernel(const float* __restrict__ s,
                                                    __nv_bfloat16* __restrict__ hi,
                                                    __nv_bfloat16* __restrict__ lo) {
    int i = (blockIdx.x * 256 + threadIdx.x) * 4;
    float4 v = *(const float4*)(s + i);
    float f[4] = {v.x, v.y, v.z, v.w};
    __nv_bfloat16 h[4], l[4];
#pragma unroll
    for (int j = 0; j < 4; j++) {
        h[j] = __float2bfloat16(f[j]);
        l[j] = __float2bfloat16(f[j] - __bfloat162float(h[j]));
    }
    *(__nv_bfloat162*)&hi[i]     = __nv_bfloat162(h[0], h[1]);
    *(__nv_bfloat162*)&hi[i + 2] = __nv_bfloat162(h[2], h[3]);
    *(__nv_bfloat162*)&lo[i]     = __nv_bfloat162(l[0], l[1]);
    *(__nv_bfloat162*)&lo[i + 2] = __nv_bfloat162(l[2], l[3]);
}

// W [Kdim, Ndim] row-major -> Wt hi/lo [Ndim, Kdim]
__global__ __launch_bounds__(256) void transsplit(const float* __restrict__ W,
                                                  __nv_bfloat16* __restrict__ thi,
                                                  __nv_bfloat16* __restrict__ tlo,
                                                  int Kdim, int Ndim) {
    __shared__ float t[32][33];
    int n0 = blockIdx.x * 32, k0 = blockIdx.y * 32;
    int tx = threadIdx.x, ty = threadIdx.y;   // (32,8)
#pragma unroll
    for (int j = 0; j < 32; j += 8)
        t[ty + j][tx] = W[(size_t)(k0 + ty + j) * Ndim + n0 + tx];
    __syncthreads();
#pragma unroll
    for (int j = 0; j < 32; j += 8) {
        float v = t[tx][ty + j];
        __nv_bfloat16 h = __float2bfloat16(v);
        size_t o = (size_t)(n0 + ty + j) * Kdim + k0 + tx;
        thi[o] = h;
        tlo[o] = __float2bfloat16(v - __bfloat162float(h));
    }
}

// ---------------------------------------------------------------------------
// HMMA GEMM: C[M,Ncols] = A[M,1024] @ Bt[Ncols,1024]^T, bf16 2-term split.
// 128x128 tile / block, 256 threads (8 warps, 4x2), K-chunk 32, double buffer.
// mode 0: C -> Cout row-major;  mode 1: scatter to g_q/g_k/g_v.
// ---------------------------------------------------------------------------
#define KC 32
#define LDP 40                      // smem row stride in bf16 (80 bytes)
#define TILE_B (128 * LDP * 2)      // 10240 bytes per tile
#define BUF_B  (4 * TILE_B)         // Ahi,Alo,Bhi,Blo

__global__ __launch_bounds__(256)
void mma_gemm(const __nv_bfloat16* __restrict__ Ahi, const __nv_bfloat16* __restrict__ Alo,
              const __nv_bfloat16* __restrict__ Bhi, const __nv_bfloat16* __restrict__ Blo,
              int Ncols, float* __restrict__ Cout, int mode) {
    extern __shared__ char smem[];
    uint32_t sb = smem_u32(smem);

    int tid = threadIdx.x, wid = tid >> 5, lane = tid & 31;
    int wm = wid & 3, wn = wid >> 2;           // warp tile: rows wm*32, cols wn*64
    int m0 = blockIdx.y * 128, n0 = blockIdx.x * 128;

    // global load coords (per tile: 2 uint4 per thread)
    int r_ld  = tid >> 2;            // 0..63  (+64 for i=1)
    int c8_ld = (tid & 3) * 8;       // bf16 col offset
    const __nv_bfloat16* srcs[4] = {
        Ahi + (size_t)m0 * GK, Alo + (size_t)m0 * GK,
        Bhi + (size_t)n0 * GK, Blo + (size_t)n0 * GK };

    // ldmatrix addresses (byte offsets inside one buffer)
    // A: row = wm*32 + tm*16 + (lane&15), col = ks*16 + (lane>>4)*8
    uint32_t a_off = (uint32_t)((wm * 32 + (lane & 15)) * LDP + (lane >> 4) * 8) * 2;
    // B: row(n) = wn*64 + pair*16 + (lane&7) + (lane>>4)*8, col = ks*16 + ((lane>>3)&1)*8
    uint32_t b_off = (uint32_t)((wn * 64 + (lane & 7) + (lane >> 4) * 8) * LDP
                                + ((lane >> 3) & 1) * 8) * 2;

    float acc[2][8][4];
#pragma unroll
    for (int i = 0; i < 2; i++)
#pragma unroll
        for (int j = 0; j < 8; j++)
#pragma unroll
            for (int k = 0; k < 4; k++) acc[i][j][k] = 0.f;

    uint4 pf[4][2];
    // prefetch chunk 0
#pragma unroll
    for (int t = 0; t < 4; t++)
#pragma unroll
        for (int i = 0; i < 2; i++)
            pf[t][i] = *(const uint4*)(srcs[t] + (size_t)(r_ld + i * 64) * GK + c8_ld);
    {   // store chunk 0 into buf0
        char* base = smem;
#pragma unroll
        for (int t = 0; t < 4; t++)
#pragma unroll
            for (int i = 0; i < 2; i++)
                *(uint4*)(base + t * TILE_B + ((r_ld + i * 64) * LDP + c8_ld) * 2) = pf[t][i];
    }
    __syncthreads();

    const int NCH = GK / KC;   // 32
    for (int kc = 0; kc < NCH; kc++) {
        int buf = kc & 1;
        if (kc + 1 < NCH) {
            size_t go = (size_t)(kc + 1) * KC;
#pragma unroll
            for (int t = 0; t < 4; t++)
#pragma unroll
                for (int i = 0; i < 2; i++)
                    pf[t][i] = *(const uint4*)(srcs[t] + (size_t)(r_ld + i * 64) * GK + go + c8_ld);
        }

        uint32_t sAh = sb + buf * BUF_B + a_off;
        uint32_t sAl = sAh + TILE_B;
        uint32_t sBh = sb + buf * BUF_B + 2 * TILE_B + b_off;
        uint32_t sBl = sBh + TILE_B;

#pragma unroll
        for (int ks = 0; ks < 2; ks++) {
            uint32_t kb = (uint32_t)(ks * 16) * 2;
            uint32_t ah[2][4], al[2][4];
#pragma unroll
            for (int tm = 0; tm < 2; tm++) {
                uint32_t ro = (uint32_t)(tm * 16 * LDP) * 2;
                ldsm4(ah[tm], sAh + ro + kb);
                ldsm4(al[tm], sAl + ro + kb);
            }
#pragma unroll
            for (int pr = 0; pr < 4; pr++) {
                uint32_t po = (uint32_t)(pr * 16 * LDP) * 2;
                uint32_t bh[4], bl[4];
                ldsm4(bh, sBh + po + kb);
                ldsm4(bl, sBl + po + kb);
#pragma unroll
                for (int hf = 0; hf < 2; hf++) {
                    int tn = pr * 2 + hf;
#pragma unroll
                    for (int tm = 0; tm < 2; tm++) {
                        mma16816(acc[tm][tn], ah[tm], bh + hf * 2);
                        mma16816(acc[tm][tn], ah[tm], bl + hf * 2);
                        mma16816(acc[tm][tn], al[tm], bh + hf * 2);
                    }
                }
            }
        }

        if (kc + 1 < NCH) {
            char* base = smem + (1 - buf) * BUF_B;
#pragma unroll
            for (int t = 0; t < 4; t++)
#pragma unroll
                for (int i = 0; i < 2; i++)
                    *(uint4*)(base + t * TILE_B + ((r_ld + i * 64) * LDP + c8_ld) * 2) = pf[t][i];
            __syncthreads();
        }
    }

    // ---- epilogue: acc fragment -> global ----
    int rbase = m0 + wm * 32 + (lane >> 2);
    int cbase = n0 + wn * 64 + (lane & 3) * 2;
#pragma unroll
    for (int tm = 0; tm < 2; tm++) {
#pragma unroll
        for (int tn = 0; tn < 8; tn++) {
            int n = cbase + tn * 8;
#pragma unroll
            for (int half = 0; half < 2; half++) {
                int m = rbase + tm * 16 + half * 8;
                float2 v = make_float2(acc[tm][tn][half * 2], acc[tm][tn][half * 2 + 1]);
                if (mode == 0) {
                    *(float2*)&Cout[(size_t)m * Ncols + n] = v;
                } else {
                    int which = n >> 10, h = (n & 1023) >> 6, d = n & 63;
                    float* dst = (which == 0) ? g_q : ((which == 1) ? g_k : g_v);
                    int b = m >> 11, t = m & 2047;
                    *(float2*)&dst[(((size_t)b * Hh + h) * Tt + t) * HDd + d] = v;
                }
            }
        }
    }
}

// ---------------- flash attention (unchanged) ----------------
__global__ __launch_bounds__(256) void attn_kernel(
    const float* __restrict__ graph_adj, const int* __restrict__ edge_types,
    const float* __restrict__ adj_bias, const float* __restrict__ edge_table) {

    extern __shared__ float sm[];
    float* Qs  = sm;
    float* Kt  = Qs + 64 * 68;
    float* Vs  = Kt + 64 * 68;
    float* Ss  = Vs + 64 * 68;
    float* m_s = Ss + 64 * 68;
    float* l_s = m_s + 64;
    float* a_s = l_s + 64;
    float* et  = a_s + 64;

    int tid = threadIdx.x;
    int tx = tid % 16, ty = tid / 16;
    int lane = tid & 31, w = tid >> 5;

    int qt = blockIdx.x, h = blockIdx.y, b = blockIdx.z;
    int q0 = qt * 64;
    const float scale = 0.125f;
    float bias_h = adj_bias[h];

    for (int i = tid; i < NEe * Hh; i += 256) et[i] = edge_table[i];

    {
        const float* qb = &g_q[((b * Hh + h) * Tt + q0) * HDd];
        for (int i = tid; i < 64 * 16; i += 256) {
            int r = i / 16, c4 = (i % 16) * 4;
            float4 v = *(const float4*)&qb[r * 64 + c4];
            Qs[r * 68 + c4 + 0] = v.x * scale;
            Qs[r * 68 + c4 + 1] = v.y * scale;
            Qs[r * 68 + c4 + 2] = v.z * scale;
            Qs[r * 68 + c4 + 3] = v.w * scale;
        }
    }
    if (tid < 64) { m_s[tid] = -1e30f; l_s[tid] = 0.f; }

    float O[4][4] = {};
    __syncthreads();

    for (int jt = 0; jt <= qt; jt++) {
        int k0 = jt * 64;
        const float* kb = &g_k[((b * Hh + h) * Tt + k0) * HDd];
        const float* vb = &g_v[((b * Hh + h) * Tt + k0) * HDd];
        for (int i = tid; i < 64 * 16; i += 256) {
            int r = i / 16, c4 = (i % 16) * 4;
            float4 kv = *(const float4*)&kb[r * 64 + c4];
            Kt[(c4 + 0) * 68 + r] = kv.x;
            Kt[(c4 + 1) * 68 + r] = kv.y;
            Kt[(c4 + 2) * 68 + r] = kv.z;
            Kt[(c4 + 3) * 68 + r] = kv.w;
            *(float4*)&Vs[r * 68 + c4] = *(const float4*)&vb[r * 64 + c4];
        }
        __syncthreads();

        float s[4][4] = {};
#pragma unroll 8
        for (int d = 0; d < 64; d++) {
            float a0 = Qs[(ty * 4 + 0) * 68 + d];
            float a1 = Qs[(ty * 4 + 1) * 68 + d];
            float a2 = Qs[(ty * 4 + 2) * 68 + d];
            float a3 = Qs[(ty * 4 + 3) * 68 + d];
            float4 kr = *(float4*)&Kt[d * 68 + tx * 4];
            float bv[4] = {kr.x, kr.y, kr.z, kr.w};
#pragma unroll
            for (int j = 0; j < 4; j++) {
                s[0][j] += a0 * bv[j];
                s[1][j] += a1 * bv[j];
                s[2][j] += a2 * bv[j];
                s[3][j] += a3 * bv[j];
            }
        }

        int qg0 = q0 + ty * 4;
        int kg0 = k0 + tx * 4;
#pragma unroll
        for (int i = 0; i < 4; i++) {
            int qg = qg0 + i;
            float4 ga = *(const float4*)&graph_adj[(b * Tt + qg) * Tt + kg0];
            int4  ev  = *(const int4*)&edge_types[(b * Tt + qg) * Tt + kg0];
            float sv[4];
            sv[0] = s[i][0] + bias_h * ga.x + et[ev.x * Hh + h];
            sv[1] = s[i][1] + bias_h * ga.y + et[ev.y * Hh + h];
            sv[2] = s[i][2] + bias_h * ga.z + et[ev.z * Hh + h];
            sv[3] = s[i][3] + bias_h * ga.w + et[ev.w * Hh + h];
#pragma unroll
            for (int j = 0; j < 4; j++)
                if (kg0 + j > qg) sv[j] = -1e30f;
            *(float4*)&Ss[(ty * 4 + i) * 68 + tx * 4] =
                make_float4(sv[0], sv[1], sv[2], sv[3]);
        }
        __syncthreads();

        for (int rr = 0; rr < 8; rr++) {
            int r = w * 8 + rr;
            float v0 = Ss[r * 68 + lane];
            float v1 = Ss[r * 68 + lane + 32];
            float mx = fmaxf(v0, v1);
#pragma unroll
            for (int o = 16; o; o >>= 1)
                mx = fmaxf(mx, __shfl_xor_sync(0xffffffffu, mx, o));
            float mprev = m_s[r];
            float mnew = fmaxf(mprev, mx);
            float p0 = __expf(v0 - mnew);
            float p1 = __expf(v1 - mnew);
            Ss[r * 68 + lane] = p0;
            Ss[r * 68 + lane + 32] = p1;
            float sum = p0 + p1;
#pragma unroll
            for (int o = 16; o; o >>= 1)
                sum += __shfl_xor_sync(0xffffffffu, sum, o);
            if (lane == 0) {
                float alpha = expf(mprev - mnew);
                m_s[r] = mnew;
                l_s[r] = l_s[r] * alpha + sum;
                a_s[r] = alpha;
            }
        }
        __syncthreads();

        float al[4];
#pragma unroll
        for (int i = 0; i < 4; i++) al[i] = a_s[ty * 4 + i];
#pragma unroll
        for (int i = 0; i < 4; i++)
#pragma unroll
            for (int j = 0; j < 4; j++) O[i][j] *= al[i];

#pragma unroll 8
        for (int kk = 0; kk < 64; kk++) {
            float a0 = Ss[(ty * 4 + 0) * 68 + kk];
            float a1 = Ss[(ty * 4 + 1) * 68 + kk];
            float a2 = Ss[(ty * 4 + 2) * 68 + kk];
            float a3 = Ss[(ty * 4 + 3) * 68 + kk];
            float4 vr = *(float4*)&Vs[kk * 68 + tx * 4];
            float bv[4] = {vr.x, vr.y, vr.z, vr.w};
#pragma unroll
            for (int j = 0; j < 4; j++) {
                O[0][j] += a0 * bv[j];
                O[1][j] += a1 * bv[j];
                O[2][j] += a2 * bv[j];
                O[3][j] += a3 * bv[j];
            }
        }
        __syncthreads();
    }

#pragma unroll
    for (int i = 0; i < 4; i++) {
        int r = ty * 4 + i;
        float inv = 1.0f / l_s[r];
        int qg = q0 + r;
        float4 o = make_float4(O[i][0] * inv, O[i][1] * inv,
                               O[i][2] * inv, O[i][3] * inv);
        *(float4*)&g_ao[(b * Tt + qg) * Dd + h * HDd + tx * 4] = o;
    }
}

// ---------------------------------------------------------------------------
extern "C" void kernel_launch(void* const* d_in, const int* in_sizes, int n_in,
                              void* d_out, int out_size) {
    const float* x     = (const float*)d_in[0];
    const float* gadj  = (const float*)d_in[1];
    const int*   etyp  = (const int*)d_in[2];
    const float* wqkv  = (const float*)d_in[3];
    const float* wproj = (const float*)d_in[4];
    const float* abias = (const float*)d_in[5];
    const float* etab  = (const float*)d_in[6];
    float* out = (float*)d_out;

    __nv_bfloat16 *xhi, *xlo, *wqhi, *wqlo, *wphi, *wplo, *aohi, *aolo;
    cudaGetSymbolAddress((void**)&xhi,  g_xhi);  cudaGetSymbolAddress((void**)&xlo,  g_xlo);
    cudaGetSymbolAddress((void**)&wqhi, g_wqThi); cudaGetSymbolAddress((void**)&wqlo, g_wqTlo);
    cudaGetSymbolAddress((void**)&wphi, g_wpThi); cudaGetSymbolAddress((void**)&wplo, g_wpTlo);
    cudaGetSymbolAddress((void**)&aohi, g_aohi); cudaGetSymbolAddress((void**)&aolo, g_aolo);
    float* ao; cudaGetSymbolAddress((void**)&ao, g_ao);

    const int SHM = 2 * BUF_B;   // 81920
    cudaFuncSetAttribute(mma_gemm, cudaFuncAttributeMaxDynamicSharedMemorySize, SHM);

    split_kernel<<<(Bb * Tt * Dd) / 1024, 256>>>(x, xhi, xlo);
    transsplit<<<dim3(3 * Dd / 32, Dd / 32), dim3(32, 8)>>>(wqkv, wqhi, wqlo, Dd, 3 * Dd);
    transsplit<<<dim3(Dd / 32, Dd / 32), dim3(32, 8)>>>(wproj, wphi, wplo, Dd, Dd);

    mma_gemm<<<dim3(3 * Dd / 128, Bb * Tt / 128), 256, SHM>>>(
        xhi, xlo, wqhi, wqlo, 3 * Dd, nullptr, 1);

    size_t shm_a = (size_t)(4 * 64 * 68 + 3 * 64 + NEe * Hh) * sizeof(float);
    cudaFuncSetAttribute(attn_kernel,
                         cudaFuncAttributeMaxDynamicSharedMemorySize, (int)shm_a);
    attn_kernel<<<dim3(Tt / 64, Hh, Bb), 256, shm_a>>>(gadj, etyp, abias, etab);

    split_kernel<<<(Bb * Tt * Dd) / 1024, 256>>>(ao, aohi, aolo);
    mma_gemm<<<dim3(Dd / 128, Bb * Tt / 128), 256, SHM>>>(
        aohi, aolo, wphi, wplo, Dd, out, 0);
}

// round 4
// speedup vs baseline: 1.5131x; 1.0173x over previous
#include <cuda_runtime.h>
#include <cuda_bf16.h>
#include <math.h>
#include <cstdint>

#define Bb 2
#define Tt 2048
#define Dd 1024
#define Hh 16
#define HDd 64
#define NEe 17
#define GK 1024

// ---------------- scratch globals ----------------
__device__ float g_q[Bb*Hh*Tt*HDd];
__device__ float g_k[Bb*Hh*Tt*HDd];
__device__ float g_v[Bb*Hh*Tt*HDd];
__device__ float g_ao[Bb*Tt*Dd];

__device__ __nv_bfloat16 g_xhi[Bb*Tt*Dd],  g_xlo[Bb*Tt*Dd];
__device__ __nv_bfloat16 g_wqThi[3*Dd*Dd], g_wqTlo[3*Dd*Dd];   // Wqkv^T [3072,1024]
__device__ __nv_bfloat16 g_wpThi[Dd*Dd],   g_wpTlo[Dd*Dd];     // Wproj^T [1024,1024]
__device__ __nv_bfloat16 g_aohi[Bb*Tt*Dd], g_aolo[Bb*Tt*Dd];

// ---------------- helpers ----------------
__device__ __forceinline__ uint32_t smem_u32(const void* p) {
    uint32_t a;
    asm("{ .reg .u64 t; cvta.to.shared.u64 t, %1; cvt.u32.u64 %0, t; }" : "=r"(a) : "l"(p));
    return a;
}

__device__ __forceinline__ void ldsm4(uint32_t* r, uint32_t addr) {
    asm volatile("ldmatrix.sync.aligned.m8n8.x4.shared.b16 {%0,%1,%2,%3}, [%4];"
        : "=r"(r[0]), "=r"(r[1]), "=r"(r[2]), "=r"(r[3]) : "r"(addr));
}

__device__ __forceinline__ void mma16816(float* c, const uint32_t* a, const uint32_t* b) {
    asm volatile("mma.sync.aligned.m16n8k16.row.col.f32.bf16.bf16.f32 "
        "{%0,%1,%2,%3}, {%4,%5,%6,%7}, {%8,%9}, {%0,%1,%2,%3};"
        : "+f"(c[0]), "+f"(c[1]), "+f"(c[2]), "+f"(c[3])
        : "r"(a[0]), "r"(a[1]), "r"(a[2]), "r"(a[3]), "r"(b[0]), "r"(b[1]));
}

// ---------------- prep kernels ----------------
__global__ __launch_bounds__(256) void split_kernel(const float* __restrict__ s,
                                                    __nv_bfloat16* __restrict__ hi,
                                                    __nv_bfloat16* __restrict__ lo) {
    int i = (blockIdx.x * 256 + threadIdx.x) * 4;
    float4 v = *(const float4*)(s + i);
    float f[4] = {v.x, v.y, v.z, v.w};
    __nv_bfloat16 h[4], l[4];
#pragma unroll
    for (int j = 0; j < 4; j++) {
        h[j] = __float2bfloat16(f[j]);
        l[j] = __float2bfloat16(f[j] - __bfloat162float(h[j]));
    }
    *(__nv_bfloat162*)&hi[i]     = __nv_bfloat162(h[0], h[1]);
    *(__nv_bfloat162*)&hi[i + 2] = __nv_bfloat162(h[2], h[3]);
    *(__nv_bfloat162*)&lo[i]     = __nv_bfloat162(l[0], l[1]);
    *(__nv_bfloat162*)&lo[i + 2] = __nv_bfloat162(l[2], l[3]);
}

// W [Kdim, Ndim] row-major -> Wt hi/lo [Ndim, Kdim]
__global__ __launch_bounds__(256) void transsplit(const float* __restrict__ W,
                                                  __nv_bfloat16* __restrict__ thi,
                                                  __nv_bfloat16* __restrict__ tlo,
                                                  int Kdim, int Ndim) {
    __shared__ float t[32][33];
    int n0 = blockIdx.x * 32, k0 = blockIdx.y * 32;
    int tx = threadIdx.x, ty = threadIdx.y;   // (32,8)
#pragma unroll
    for (int j = 0; j < 32; j += 8)
        t[ty + j][tx] = W[(size_t)(k0 + ty + j) * Ndim + n0 + tx];
    __syncthreads();
#pragma unroll
    for (int j = 0; j < 32; j += 8) {
        float v = t[tx][ty + j];
        __nv_bfloat16 h = __float2bfloat16(v);
        size_t o = (size_t)(n0 + ty + j) * Kdim + k0 + tx;
        thi[o] = h;
        tlo[o] = __float2bfloat16(v - __bfloat162float(h));
    }
}

// ---------------------------------------------------------------------------
// HMMA GEMM: C[M,Ncols] = A[M,1024] @ Bt[Ncols,1024]^T, bf16 2-term split.
// 128x128 tile / block, 256 threads (8 warps, 4x2), K-chunk 32, double buffer.
// mode 0: C -> Cout row-major;  mode 1: scatter to g_q/g_k/g_v.
// ---------------------------------------------------------------------------
#define KC 32
#define LDP 40                      // smem row stride in bf16 (80 bytes)
#define TILE_B (128 * LDP * 2)      // 10240 bytes per tile
#define BUF_B  (4 * TILE_B)         // Ahi,Alo,Bhi,Blo

__global__ __launch_bounds__(256)
void mma_gemm(const __nv_bfloat16* __restrict__ Ahi, const __nv_bfloat16* __restrict__ Alo,
              const __nv_bfloat16* __restrict__ Bhi, const __nv_bfloat16* __restrict__ Blo,
              int Ncols, float* __restrict__ Cout, int mode) {
    extern __shared__ char smem[];
    uint32_t sb = smem_u32(smem);

    int tid = threadIdx.x, wid = tid >> 5, lane = tid & 31;
    int wm = wid & 3, wn = wid >> 2;           // warp tile: rows wm*32, cols wn*64
    int m0 = blockIdx.y * 128, n0 = blockIdx.x * 128;

    // global load coords (per tile: 2 uint4 per thread)
    int r_ld  = tid >> 2;            // 0..63  (+64 for i=1)
    int c8_ld = (tid & 3) * 8;       // bf16 col offset
    const __nv_bfloat16* srcs[4] = {
        Ahi + (size_t)m0 * GK, Alo + (size_t)m0 * GK,
        Bhi + (size_t)n0 * GK, Blo + (size_t)n0 * GK };

    // ldmatrix addresses (byte offsets inside one buffer)
    // A: row = wm*32 + tm*16 + (lane&15), col = ks*16 + (lane>>4)*8
    uint32_t a_off = (uint32_t)((wm * 32 + (lane & 15)) * LDP + (lane >> 4) * 8) * 2;
    // B: row(n) = wn*64 + pair*16 + (lane&7) + (lane>>4)*8, col = ks*16 + ((lane>>3)&1)*8
    uint32_t b_off = (uint32_t)((wn * 64 + (lane & 7) + (lane >> 4) * 8) * LDP
                                + ((lane >> 3) & 1) * 8) * 2;

    float acc[2][8][4];
#pragma unroll
    for (int i = 0; i < 2; i++)
#pragma unroll
        for (int j = 0; j < 8; j++)
#pragma unroll
            for (int k = 0; k < 4; k++) acc[i][j][k] = 0.f;

    uint4 pf[4][2];
    // prefetch chunk 0
#pragma unroll
    for (int t = 0; t < 4; t++)
#pragma unroll
        for (int i = 0; i < 2; i++)
            pf[t][i] = *(const uint4*)(srcs[t] + (size_t)(r_ld + i * 64) * GK + c8_ld);
    {   // store chunk 0 into buf0
        char* base = smem;
#pragma unroll
        for (int t = 0; t < 4; t++)
#pragma unroll
            for (int i = 0; i < 2; i++)
                *(uint4*)(base + t * TILE_B + ((r_ld + i * 64) * LDP + c8_ld) * 2) = pf[t][i];
    }
    __syncthreads();

    const int NCH = GK / KC;   // 32
    for (int kc = 0; kc < NCH; kc++) {
        int buf = kc & 1;
        if (kc + 1 < NCH) {
            size_t go = (size_t)(kc + 1) * KC;
#pragma unroll
            for (int t = 0; t < 4; t++)
#pragma unroll
                for (int i = 0; i < 2; i++)
                    pf[t][i] = *(const uint4*)(srcs[t] + (size_t)(r_ld + i * 64) * GK + go + c8_ld);
        }

        uint32_t sAh = sb + buf * BUF_B + a_off;
        uint32_t sAl = sAh + TILE_B;
        uint32_t sBh = sb + buf * BUF_B + 2 * TILE_B + b_off;
        uint32_t sBl = sBh + TILE_B;

#pragma unroll
        for (int ks = 0; ks < 2; ks++) {
            uint32_t kb = (uint32_t)(ks * 16) * 2;
            uint32_t ah[2][4], al[2][4];
#pragma unroll
            for (int tm = 0; tm < 2; tm++) {
                uint32_t ro = (uint32_t)(tm * 16 * LDP) * 2;
                ldsm4(ah[tm], sAh + ro + kb);
                ldsm4(al[tm], sAl + ro + kb);
            }
#pragma unroll
            for (int pr = 0; pr < 4; pr++) {
                uint32_t po = (uint32_t)(pr * 16 * LDP) * 2;
                uint32_t bh[4], bl[4];
                ldsm4(bh, sBh + po + kb);
                ldsm4(bl, sBl + po + kb);
#pragma unroll
                for (int hf = 0; hf < 2; hf++) {
                    int tn = pr * 2 + hf;
#pragma unroll
                    for (int tm = 0; tm < 2; tm++) {
                        mma16816(acc[tm][tn], ah[tm], bh + hf * 2);
                        mma16816(acc[tm][tn], ah[tm], bl + hf * 2);
                        mma16816(acc[tm][tn], al[tm], bh + hf * 2);
                    }
                }
            }
        }

        if (kc + 1 < NCH) {
            char* base = smem + (1 - buf) * BUF_B;
#pragma unroll
            for (int t = 0; t < 4; t++)
#pragma unroll
                for (int i = 0; i < 2; i++)
                    *(uint4*)(base + t * TILE_B + ((r_ld + i * 64) * LDP + c8_ld) * 2) = pf[t][i];
            __syncthreads();
        }
    }

    // ---- epilogue: acc fragment -> global ----
    int rbase = m0 + wm * 32 + (lane >> 2);
    int cbase = n0 + wn * 64 + (lane & 3) * 2;
#pragma unroll
    for (int tm = 0; tm < 2; tm++) {
#pragma unroll
        for (int tn = 0; tn < 8; tn++) {
            int n = cbase + tn * 8;
#pragma unroll
            for (int half = 0; half < 2; half++) {
                int m = rbase + tm * 16 + half * 8;
                float2 v = make_float2(acc[tm][tn][half * 2], acc[tm][tn][half * 2 + 1]);
                if (mode == 0) {
                    *(float2*)&Cout[(size_t)m * Ncols + n] = v;
                } else {
                    int which = n >> 10, h = (n & 1023) >> 6, d = n & 63;
                    float* dst = (which == 0) ? g_q : ((which == 1) ? g_k : g_v);
                    int b = m >> 11, t = m & 2047;
                    *(float2*)&dst[(((size_t)b * Hh + h) * Tt + t) * HDd + d] = v;
                }
            }
        }
    }
}

// ---------------- flash attention (unchanged) ----------------
__global__ __launch_bounds__(256) void attn_kernel(
    const float* __restrict__ graph_adj, const int* __restrict__ edge_types,
    const float* __restrict__ adj_bias, const float* __restrict__ edge_table) {

    extern __shared__ float sm[];
    float* Qs  = sm;
    float* Kt  = Qs + 64 * 68;
    float* Vs  = Kt + 64 * 68;
    float* Ss  = Vs + 64 * 68;
    float* m_s = Ss + 64 * 68;
    float* l_s = m_s + 64;
    float* a_s = l_s + 64;
    float* et  = a_s + 64;

    int tid = threadIdx.x;
    int tx = tid % 16, ty = tid / 16;
    int lane = tid & 31, w = tid >> 5;

    int qt = blockIdx.x, h = blockIdx.y, b = blockIdx.z;
    int q0 = qt * 64;
    const float scale = 0.125f;
    float bias_h = adj_bias[h];

    for (int i = tid; i < NEe * Hh; i += 256) et[i] = edge_table[i];

    {
        const float* qb = &g_q[((b * Hh + h) * Tt + q0) * HDd];
        for (int i = tid; i < 64 * 16; i += 256) {
            int r = i / 16, c4 = (i % 16) * 4;
            float4 v = *(const float4*)&qb[r * 64 + c4];
            Qs[r * 68 + c4 + 0] = v.x * scale;
            Qs[r * 68 + c4 + 1] = v.y * scale;
            Qs[r * 68 + c4 + 2] = v.z * scale;
            Qs[r * 68 + c4 + 3] = v.w * scale;
        }
    }
    if (tid < 64) { m_s[tid] = -1e30f; l_s[tid] = 0.f; }

    float O[4][4] = {};
    __syncthreads();

    for (int jt = 0; jt <= qt; jt++) {
        int k0 = jt * 64;
        const float* kb = &g_k[((b * Hh + h) * Tt + k0) * HDd];
        const float* vb = &g_v[((b * Hh + h) * Tt + k0) * HDd];
        for (int i = tid; i < 64 * 16; i += 256) {
            int r = i / 16, c4 = (i % 16) * 4;
            float4 kv = *(const float4*)&kb[r * 64 + c4];
            Kt[(c4 + 0) * 68 + r] = kv.x;
            Kt[(c4 + 1) * 68 + r] = kv.y;
            Kt[(c4 + 2) * 68 + r] = kv.z;
            Kt[(c4 + 3) * 68 + r] = kv.w;
            *(float4*)&Vs[r * 68 + c4] = *(const float4*)&vb[r * 64 + c4];
        }
        __syncthreads();

        float s[4][4] = {};
#pragma unroll 8
        for (int d = 0; d < 64; d++) {
            float a0 = Qs[(ty * 4 + 0) * 68 + d];
            float a1 = Qs[(ty * 4 + 1) * 68 + d];
            float a2 = Qs[(ty * 4 + 2) * 68 + d];
            float a3 = Qs[(ty * 4 + 3) * 68 + d];
            float4 kr = *(float4*)&Kt[d * 68 + tx * 4];
            float bv[4] = {kr.x, kr.y, kr.z, kr.w};
#pragma unroll
            for (int j = 0; j < 4; j++) {
                s[0][j] += a0 * bv[j];
                s[1][j] += a1 * bv[j];
                s[2][j] += a2 * bv[j];
                s[3][j] += a3 * bv[j];
            }
        }

        int qg0 = q0 + ty * 4;
        int kg0 = k0 + tx * 4;
#pragma unroll
        for (int i = 0; i < 4; i++) {
            int qg = qg0 + i;
            float4 ga = *(const float4*)&graph_adj[(b * Tt + qg) * Tt + kg0];
            int4  ev  = *(const int4*)&edge_types[(b * Tt + qg) * Tt + kg0];
            float sv[4];
            sv[0] = s[i][0] + bias_h * ga.x + et[ev.x * Hh + h];
            sv[1] = s[i][1] + bias_h * ga.y + et[ev.y * Hh + h];
            sv[2] = s[i][2] + bias_h * ga.z + et[ev.z * Hh + h];
            sv[3] = s[i][3] + bias_h * ga.w + et[ev.w * Hh + h];
#pragma unroll
            for (int j = 0; j < 4; j++)
                if (kg0 + j > qg) sv[j] = -1e30f;
            *(float4*)&Ss[(ty * 4 + i) * 68 + tx * 4] =
                make_float4(sv[0], sv[1], sv[2], sv[3]);
        }
        __syncthreads();

        for (int rr = 0; rr < 8; rr++) {
            int r = w * 8 + rr;
            float v0 = Ss[r * 68 + lane];
            float v1 = Ss[r * 68 + lane + 32];
            float mx = fmaxf(v0, v1);
#pragma unroll
            for (int o = 16; o; o >>= 1)
                mx = fmaxf(mx, __shfl_xor_sync(0xffffffffu, mx, o));
            float mprev = m_s[r];
            float mnew = fmaxf(mprev, mx);
            float p0 = __expf(v0 - mnew);
            float p1 = __expf(v1 - mnew);
            Ss[r * 68 + lane] = p0;
            Ss[r * 68 + lane + 32] = p1;
            float sum = p0 + p1;
#pragma unroll
            for (int o = 16; o; o >>= 1)
                sum += __shfl_xor_sync(0xffffffffu, sum, o);
            if (lane == 0) {
                float alpha = expf(mprev - mnew);
                m_s[r] = mnew;
                l_s[r] = l_s[r] * alpha + sum;
                a_s[r] = alpha;
            }
        }
        __syncthreads();

        float al[4];
#pragma unroll
        for (int i = 0; i < 4; i++) al[i] = a_s[ty * 4 + i];
#pragma unroll
        for (int i = 0; i < 4; i++)
#pragma unroll
            for (int j = 0; j < 4; j++) O[i][j] *= al[i];

#pragma unroll 8
        for (int kk = 0; kk < 64; kk++) {
            float a0 = Ss[(ty * 4 + 0) * 68 + kk];
            float a1 = Ss[(ty * 4 + 1) * 68 + kk];
            float a2 = Ss[(ty * 4 + 2) * 68 + kk];
            float a3 = Ss[(ty * 4 + 3) * 68 + kk];
            float4 vr = *(float4*)&Vs[kk * 68 + tx * 4];
            float bv[4] = {vr.x, vr.y, vr.z, vr.w};
#pragma unroll
            for (int j = 0; j < 4; j++) {
                O[0][j] += a0 * bv[j];
                O[1][j] += a1 * bv[j];
                O[2][j] += a2 * bv[j];
                O[3][j] += a3 * bv[j];
            }
        }
        __syncthreads();
    }

#pragma unroll
    for (int i = 0; i < 4; i++) {
        int r = ty * 4 + i;
        float inv = 1.0f / l_s[r];
        int qg = q0 + r;
        float4 o = make_float4(O[i][0] * inv, O[i][1] * inv,
                               O[i][2] * inv, O[i][3] * inv);
        *(float4*)&g_ao[(b * Tt + qg) * Dd + h * HDd + tx * 4] = o;
    }
}

// ---------------------------------------------------------------------------
extern "C" void kernel_launch(void* const* d_in, const int* in_sizes, int n_in,
                              void* d_out, int out_size) {
    const float* x     = (const float*)d_in[0];
    const float* gadj  = (const float*)d_in[1];
    const int*   etyp  = (const int*)d_in[2];
    const float* wqkv  = (const float*)d_in[3];
    const float* wproj = (const float*)d_in[4];
    const float* abias = (const float*)d_in[5];
    const float* etab  = (const float*)d_in[6];
    float* out = (float*)d_out;

    __nv_bfloat16 *xhi, *xlo, *wqhi, *wqlo, *wphi, *wplo, *aohi, *aolo;
    cudaGetSymbolAddress((void**)&xhi,  g_xhi);  cudaGetSymbolAddress((void**)&xlo,  g_xlo);
    cudaGetSymbolAddress((void**)&wqhi, g_wqThi); cudaGetSymbolAddress((void**)&wqlo, g_wqTlo);
    cudaGetSymbolAddress((void**)&wphi, g_wpThi); cudaGetSymbolAddress((void**)&wplo, g_wpTlo);
    cudaGetSymbolAddress((void**)&aohi, g_aohi); cudaGetSymbolAddress((void**)&aolo, g_aolo);
    float* ao; cudaGetSymbolAddress((void**)&ao, g_ao);

    const int SHM = 2 * BUF_B;   // 81920
    cudaFuncSetAttribute(mma_gemm, cudaFuncAttributeMaxDynamicSharedMemorySize, SHM);

    split_kernel<<<(Bb * Tt * Dd) / 1024, 256>>>(x, xhi, xlo);
    transsplit<<<dim3(3 * Dd / 32, Dd / 32), dim3(32, 8)>>>(wqkv, wqhi, wqlo, Dd, 3 * Dd);
    transsplit<<<dim3(Dd / 32, Dd / 32), dim3(32, 8)>>>(wproj, wphi, wplo, Dd, Dd);

    mma_gemm<<<dim3(3 * Dd / 128, Bb * Tt / 128), 256, SHM>>>(
        xhi, xlo, wqhi, wqlo, 3 * Dd, nullptr, 1);

    size_t shm_a = (size_t)(4 * 64 * 68 + 3 * 64 + NEe * Hh) * sizeof(float);
    cudaFuncSetAttribute(attn_kernel,
                         cudaFuncAttributeMaxDynamicSharedMemorySize, (int)shm_a);
    attn_kernel<<<dim3(Tt / 64, Hh, Bb), 256, shm_a>>>(gadj, etyp, abias, etab);

    split_kernel<<<(Bb * Tt * Dd) / 1024, 256>>>(ao, aohi, aolo);
    mma_gemm<<<dim3(Dd / 128, Bb * Tt / 128), 256, SHM>>>(
        aohi, aolo, wphi, wplo, Dd, out, 0);
}

// round 5
// speedup vs baseline: 2.8037x; 1.8530x over previous
#include <cuda_runtime.h>
#include <cuda_bf16.h>
#include <math.h>
#include <cstdint>

#define Bb 2
#define Tt 2048
#define Dd 1024
#define Hh 16
#define HDd 64
#define NEe 17
#define GK 1024

// ---------------- scratch globals ----------------
__device__ __nv_bfloat16 g_xhi[Bb*Tt*Dd],  g_xlo[Bb*Tt*Dd];
__device__ __nv_bfloat16 g_wqThi[3*Dd*Dd], g_wqTlo[3*Dd*Dd];
__device__ __nv_bfloat16 g_wpThi[Dd*Dd],   g_wpTlo[Dd*Dd];
__device__ __nv_bfloat16 g_qhi[Bb*Hh*Tt*HDd], g_qlo[Bb*Hh*Tt*HDd];   // [b,h,t,d] *0.125
__device__ __nv_bfloat16 g_khi[Bb*Hh*Tt*HDd], g_klo[Bb*Hh*Tt*HDd];   // [b,h,t,d]
__device__ __nv_bfloat16 g_vhi[Bb*Hh*Tt*HDd], g_vlo[Bb*Hh*Tt*HDd];   // [b,h,d,t]
__device__ __nv_bfloat16 g_aohi[Bb*Tt*Dd], g_aolo[Bb*Tt*Dd];
__device__ float g_ao[Bb*Tt*Dd];
__device__ uint32_t g_pack[(size_t)Bb*Tt*Tt];

// ---------------- helpers ----------------
__device__ __forceinline__ uint32_t smem_u32(const void* p) {
    uint32_t a;
    asm("{ .reg .u64 t; cvta.to.shared.u64 t, %1; cvt.u32.u64 %0, t; }" : "=r"(a) : "l"(p));
    return a;
}
__device__ __forceinline__ void ldsm4(uint32_t* r, uint32_t addr) {
    asm volatile("ldmatrix.sync.aligned.m8n8.x4.shared.b16 {%0,%1,%2,%3}, [%4];"
        : "=r"(r[0]), "=r"(r[1]), "=r"(r[2]), "=r"(r[3]) : "r"(addr));
}
__device__ __forceinline__ void mma16816(float* c, const uint32_t* a, const uint32_t* b) {
    asm volatile("mma.sync.aligned.m16n8k16.row.col.f32.bf16.bf16.f32 "
        "{%0,%1,%2,%3}, {%4,%5,%6,%7}, {%8,%9}, {%0,%1,%2,%3};"
        : "+f"(c[0]), "+f"(c[1]), "+f"(c[2]), "+f"(c[3])
        : "r"(a[0]), "r"(a[1]), "r"(a[2]), "r"(a[3]), "r"(b[0]), "r"(b[1]));
}
__device__ __forceinline__ void pk2(float a, float b, uint32_t& hi, uint32_t& lo) {
    __nv_bfloat16 ha = __float2bfloat16(a), hb = __float2bfloat16(b);
    __nv_bfloat162 hh(ha, hb); hi = *(uint32_t*)&hh;
    __nv_bfloat162 ll(__float2bfloat16(a - __bfloat162float(ha)),
                      __float2bfloat16(b - __bfloat162float(hb)));
    lo = *(uint32_t*)&ll;
}

// ---------------- prep kernels ----------------
__global__ __launch_bounds__(256) void split_kernel(const float* __restrict__ s,
                                                    __nv_bfloat16* __restrict__ hi,
                                                    __nv_bfloat16* __restrict__ lo) {
    int i = (blockIdx.x * 256 + threadIdx.x) * 4;
    float4 v = *(const float4*)(s + i);
    float f[4] = {v.x, v.y, v.z, v.w};
    __nv_bfloat16 h[4], l[4];
#pragma unroll
    for (int j = 0; j < 4; j++) {
        h[j] = __float2bfloat16(f[j]);
        l[j] = __float2bfloat16(f[j] - __bfloat162float(h[j]));
    }
    *(__nv_bfloat162*)&hi[i]     = __nv_bfloat162(h[0], h[1]);
    *(__nv_bfloat162*)&hi[i + 2] = __nv_bfloat162(h[2], h[3]);
    *(__nv_bfloat162*)&lo[i]     = __nv_bfloat162(l[0], l[1]);
    *(__nv_bfloat162*)&lo[i + 2] = __nv_bfloat162(l[2], l[3]);
}

__global__ __launch_bounds__(256) void transsplit(const float* __restrict__ W,
                                                  __nv_bfloat16* __restrict__ thi,
                                                  __nv_bfloat16* __restrict__ tlo,
                                                  int Kdim, int Ndim) {
    __shared__ float t[32][33];
    int n0 = blockIdx.x * 32, k0 = blockIdx.y * 32;
    int tx = threadIdx.x, ty = threadIdx.y;
#pragma unroll
    for (int j = 0; j < 32; j += 8)
        t[ty + j][tx] = W[(size_t)(k0 + ty + j) * Ndim + n0 + tx];
    __syncthreads();
#pragma unroll
    for (int j = 0; j < 32; j += 8) {
        float v = t[tx][ty + j];
        __nv_bfloat16 h = __float2bfloat16(v);
        size_t o = (size_t)(n0 + ty + j) * Kdim + k0 + tx;
        thi[o] = h;
        tlo[o] = __float2bfloat16(v - __bfloat162float(h));
    }
}

__global__ __launch_bounds__(256) void pack_bias(const float* __restrict__ adj,
                                                 const int* __restrict__ ety,
                                                 uint32_t* __restrict__ out) {
    size_t i = ((size_t)blockIdx.x * 256 + threadIdx.x) * 4;
    float4 a = *(const float4*)(adj + i);
    int4 t = *(const int4*)(ety + i);
    uint4 r;
    r.x = ((uint32_t)t.x << 16) | (uint32_t)__bfloat16_as_ushort(__float2bfloat16(a.x));
    r.y = ((uint32_t)t.y << 16) | (uint32_t)__bfloat16_as_ushort(__float2bfloat16(a.y));
    r.z = ((uint32_t)t.z << 16) | (uint32_t)__bfloat16_as_ushort(__float2bfloat16(a.z));
    r.w = ((uint32_t)t.w << 16) | (uint32_t)__bfloat16_as_ushort(__float2bfloat16(a.w));
    *(uint4*)(out + i) = r;
}

// ---------------------------------------------------------------------------
// HMMA GEMM. mode 0: fp32 Cout. mode 1: QKV epilogue -> bf16 hi/lo,
//   Q pre-scaled, V transposed [b,h,d,t].
// ---------------------------------------------------------------------------
#define KC 32
#define LDP 40
#define TILE_B (128 * LDP * 2)
#define BUF_B  (4 * TILE_B)

__global__ __launch_bounds__(256)
void mma_gemm(const __nv_bfloat16* __restrict__ Ahi, const __nv_bfloat16* __restrict__ Alo,
              const __nv_bfloat16* __restrict__ Bhi, const __nv_bfloat16* __restrict__ Blo,
              int Ncols, float* __restrict__ Cout, int mode) {
    extern __shared__ char smem[];
    uint32_t sb = smem_u32(smem);
    int tid = threadIdx.x, wid = tid >> 5, lane = tid & 31;
    int wm = wid & 3, wn = wid >> 2;
    int m0 = blockIdx.y * 128, n0 = blockIdx.x * 128;

    int r_ld  = tid >> 2;
    int c8_ld = (tid & 3) * 8;
    const __nv_bfloat16* srcs[4] = {
        Ahi + (size_t)m0 * GK, Alo + (size_t)m0 * GK,
        Bhi + (size_t)n0 * GK, Blo + (size_t)n0 * GK };

    uint32_t a_off = (uint32_t)((wm * 32 + (lane & 15)) * LDP + (lane >> 4) * 8) * 2;
    uint32_t b_off = (uint32_t)((wn * 64 + (lane & 7) + (lane >> 4) * 8) * LDP
                                + ((lane >> 3) & 1) * 8) * 2;

    float acc[2][8][4];
#pragma unroll
    for (int i = 0; i < 2; i++)
#pragma unroll
        for (int j = 0; j < 8; j++)
#pragma unroll
            for (int k = 0; k < 4; k++) acc[i][j][k] = 0.f;

    uint4 pf[4][2];
#pragma unroll
    for (int t = 0; t < 4; t++)
#pragma unroll
        for (int i = 0; i < 2; i++)
            pf[t][i] = *(const uint4*)(srcs[t] + (size_t)(r_ld + i * 64) * GK + c8_ld);
    {
        char* base = smem;
#pragma unroll
        for (int t = 0; t < 4; t++)
#pragma unroll
            for (int i = 0; i < 2; i++)
                *(uint4*)(base + t * TILE_B + ((r_ld + i * 64) * LDP + c8_ld) * 2) = pf[t][i];
    }
    __syncthreads();

    const int NCH = GK / KC;
    for (int kc = 0; kc < NCH; kc++) {
        int buf = kc & 1;
        if (kc + 1 < NCH) {
            size_t go = (size_t)(kc + 1) * KC;
#pragma unroll
            for (int t = 0; t < 4; t++)
#pragma unroll
                for (int i = 0; i < 2; i++)
                    pf[t][i] = *(const uint4*)(srcs[t] + (size_t)(r_ld + i * 64) * GK + go + c8_ld);
        }
        uint32_t sAh = sb + buf * BUF_B + a_off;
        uint32_t sAl = sAh + TILE_B;
        uint32_t sBh = sb + buf * BUF_B + 2 * TILE_B + b_off;
        uint32_t sBl = sBh + TILE_B;
#pragma unroll
        for (int ks = 0; ks < 2; ks++) {
            uint32_t kb = (uint32_t)(ks * 16) * 2;
            uint32_t ah[2][4], al[2][4];
#pragma unroll
            for (int tm = 0; tm < 2; tm++) {
                uint32_t ro = (uint32_t)(tm * 16 * LDP) * 2;
                ldsm4(ah[tm], sAh + ro + kb);
                ldsm4(al[tm], sAl + ro + kb);
            }
#pragma unroll
            for (int pr = 0; pr < 4; pr++) {
                uint32_t po = (uint32_t)(pr * 16 * LDP) * 2;
                uint32_t bh[4], bl[4];
                ldsm4(bh, sBh + po + kb);
                ldsm4(bl, sBl + po + kb);
#pragma unroll
                for (int hf = 0; hf < 2; hf++) {
                    int tn = pr * 2 + hf;
#pragma unroll
                    for (int tm = 0; tm < 2; tm++) {
                        mma16816(acc[tm][tn], ah[tm], bh + hf * 2);
                        mma16816(acc[tm][tn], ah[tm], bl + hf * 2);
                        mma16816(acc[tm][tn], al[tm], bh + hf * 2);
                    }
                }
            }
        }
        if (kc + 1 < NCH) {
            char* base = smem + (1 - buf) * BUF_B;
#pragma unroll
            for (int t = 0; t < 4; t++)
#pragma unroll
                for (int i = 0; i < 2; i++)
                    *(uint4*)(base + t * TILE_B + ((r_ld + i * 64) * LDP + c8_ld) * 2) = pf[t][i];
            __syncthreads();
        }
    }

    int rbase = m0 + wm * 32 + (lane >> 2);
    int cbase = n0 + wn * 64 + (lane & 3) * 2;

    if (mode == 0) {
#pragma unroll
        for (int tm = 0; tm < 2; tm++)
#pragma unroll
            for (int tn = 0; tn < 8; tn++)
#pragma unroll
                for (int half = 0; half < 2; half++) {
                    int m = rbase + tm * 16 + half * 8;
                    *(float2*)&Cout[(size_t)m * Ncols + cbase + tn * 8] =
                        make_float2(acc[tm][tn][half * 2], acc[tm][tn][half * 2 + 1]);
                }
        return;
    }

    int which = n0 >> 10;
    if (which < 2) {
        float sc = (which == 0) ? 0.125f : 1.0f;
        __nv_bfloat16* dh = which ? g_khi : g_qhi;
        __nv_bfloat16* dl = which ? g_klo : g_qlo;
#pragma unroll
        for (int tm = 0; tm < 2; tm++)
#pragma unroll
            for (int tn = 0; tn < 8; tn++)
#pragma unroll
                for (int half = 0; half < 2; half++) {
                    int m = rbase + tm * 16 + half * 8;
                    int n = cbase + tn * 8;
                    int h = (n & 1023) >> 6, d = n & 63;
                    int bI = m >> 11, t = m & 2047;
                    size_t ix = ((size_t)(bI * Hh + h) * Tt + t) * HDd + d;
                    uint32_t uh, ul;
                    pk2(acc[tm][tn][half * 2] * sc, acc[tm][tn][half * 2 + 1] * sc, uh, ul);
                    *(uint32_t*)&dh[ix] = uh;
                    *(uint32_t*)&dl[ix] = ul;
                }
    } else {
        float* buf = (float*)smem;
        __syncthreads();
#pragma unroll
        for (int tm = 0; tm < 2; tm++)
#pragma unroll
            for (int tn = 0; tn < 8; tn++)
#pragma unroll
                for (int half = 0; half < 2; half++) {
                    int nl = wn * 64 + tn * 8 + (lane & 3) * 2;
                    int ml = wm * 32 + (lane >> 2) + tm * 16 + half * 8;
                    buf[nl * 132 + ml]       = acc[tm][tn][half * 2];
                    buf[(nl + 1) * 132 + ml] = acc[tm][tn][half * 2 + 1];
                }
        __syncthreads();
        int nl = tid >> 1, mh = (tid & 1) * 64;
        int n = n0 + nl;
        int h = (n & 1023) >> 6, d = n & 63;
        int bI = m0 >> 11, t0 = (m0 & 2047) + mh;
        size_t base = ((size_t)(bI * Hh + h) * HDd + d) * Tt + t0;
#pragma unroll
        for (int g = 0; g < 8; g++) {
            __nv_bfloat16 hi8[8], lo8[8];
#pragma unroll
            for (int e = 0; e < 8; e++) {
                float f = buf[nl * 132 + mh + g * 8 + e];
                hi8[e] = __float2bfloat16(f);
                lo8[e] = __float2bfloat16(f - __bfloat162float(hi8[e]));
            }
            *(uint4*)&g_vhi[base + g * 8] = *(uint4*)hi8;
            *(uint4*)&g_vlo[base + g * 8] = *(uint4*)lo8;
        }
    }
}

// ---------------------------------------------------------------------------
// HMMA flash attention: q-tile 128, k-tile 64, 8 warps, keys permuted per 16.
// ---------------------------------------------------------------------------
#define LQ 72
__global__ __launch_bounds__(256, 2) void attn_mma(
    const uint32_t* __restrict__ pk, const float* __restrict__ adj_bias,
    const float* __restrict__ edge_table) {
    extern __shared__ char sm[];
    __nv_bfloat16* sQh = (__nv_bfloat16*)sm;            // [128][72]
    __nv_bfloat16* sQl = sQh + 128 * LQ;
    __nv_bfloat16* sKh = sQl + 128 * LQ;                // [64][72] row=permuted key
    __nv_bfloat16* sKl = sKh + 64 * LQ;
    __nv_bfloat16* sVh = sKl + 64 * LQ;                 // [64][72] row=d, col=permuted key
    __nv_bfloat16* sVl = sVh + 64 * LQ;
    float* ets = (float*)(sVl + 64 * LQ);               // [17]
    uint32_t sB = smem_u32(sm);
    const uint32_t oQh = 0, oQl = 128*LQ*2, oKh = 2*128*LQ*2, oKl = oKh + 64*LQ*2,
                   oVh = oKl + 64*LQ*2, oVl = oVh + 64*LQ*2;

    int tid = threadIdx.x, w = tid >> 5, lane = tid & 31;
    int qt = blockIdx.x, h = blockIdx.y, b = blockIdx.z;
    int q0 = qt * 128, qw = q0 + 16 * w;
    float bco = adj_bias[h];
    if (tid < NEe) ets[tid] = edge_table[tid * Hh + h];

    {   // load Q tile (pre-scaled bf16 hi/lo)
        const __nv_bfloat16* qh = g_qhi + ((size_t)(b * Hh + h) * Tt + q0) * HDd;
        const __nv_bfloat16* ql = g_qlo + ((size_t)(b * Hh + h) * Tt + q0) * HDd;
        int r = tid >> 1, cg = (tid & 1) * 32;
#pragma unroll
        for (int u = 0; u < 4; u++) {
            *(uint4*)&sQh[r * LQ + cg + u * 8] = *(const uint4*)&qh[(size_t)r * 64 + cg + u * 8];
            *(uint4*)&sQl[r * LQ + cg + u * 8] = *(const uint4*)&ql[(size_t)r * 64 + cg + u * 8];
        }
    }

    float o[8][4];
#pragma unroll
    for (int i = 0; i < 8; i++)
#pragma unroll
        for (int j = 0; j < 4; j++) o[i][j] = 0.f;
    float m0r = -1e30f, m1r = -1e30f, l0r = 0.f, l1r = 0.f;

    int nkt = 2 * qt + 2;
    for (int jt = 0; jt < nkt; jt++) {
        int k0 = jt * 64;
        __syncthreads();
        {   // K tile: row c holds global key k0+g(c), g(c)=16*((c>>1)&3)+2*(c>>3)+(c&1)
            int c = tid >> 2, dg = (tid & 3) * 16;
            int gk = k0 + 16 * ((c >> 1) & 3) + 2 * (c >> 3) + (c & 1);
            const __nv_bfloat16* kh = g_khi + ((size_t)(b * Hh + h) * Tt + gk) * HDd;
            const __nv_bfloat16* kl = g_klo + ((size_t)(b * Hh + h) * Tt + gk) * HDd;
            *(uint4*)&sKh[c * LQ + dg]     = *(const uint4*)&kh[dg];
            *(uint4*)&sKh[c * LQ + dg + 8] = *(const uint4*)&kh[dg + 8];
            *(uint4*)&sKl[c * LQ + dg]     = *(const uint4*)&kl[dg];
            *(uint4*)&sKl[c * LQ + dg + 8] = *(const uint4*)&kl[dg + 8];
            // V^T: row d, permuted key cols; thread: d=tid>>2, a=tid&3 -> keys 16a..16a+15
            int d = tid >> 2, a = tid & 3;
            const __nv_bfloat16* vh = g_vhi + ((size_t)(b * Hh + h) * HDd + d) * Tt + k0 + 16 * a;
            const __nv_bfloat16* vl = g_vlo + ((size_t)(b * Hh + h) * HDd + d) * Tt + k0 + 16 * a;
            uint4 h0 = *(const uint4*)vh, h1 = *(const uint4*)(vh + 8);
            uint4 l0 = *(const uint4*)vl, l1 = *(const uint4*)(vl + 8);
            uint32_t* p0 = (uint32_t*)&h0; uint32_t* p1 = (uint32_t*)&h1;
            uint32_t* p2 = (uint32_t*)&l0; uint32_t* p3 = (uint32_t*)&l1;
#pragma unroll
            for (int mI = 0; mI < 4; mI++) {
                *(uint32_t*)&sVh[d * LQ + 2 * a + 8 * mI]      = p0[mI];
                *(uint32_t*)&sVh[d * LQ + 2 * a + 32 + 8 * mI] = p1[mI];
                *(uint32_t*)&sVl[d * LQ + 2 * a + 8 * mI]      = p2[mI];
                *(uint32_t*)&sVl[d * LQ + 2 * a + 32 + 8 * mI] = p3[mI];
            }
        }
        __syncthreads();

        bool active = (k0 <= qw + 15);
        if (!active) continue;

        float s[8][4];
#pragma unroll
        for (int i = 0; i < 8; i++)
#pragma unroll
            for (int j = 0; j < 4; j++) s[i][j] = 0.f;

        // S = Q K^T
        uint32_t acol = (uint32_t)((lane >> 4) * 8) * 2;
        uint32_t arow = (uint32_t)((16 * w + (lane & 15)) * LQ) * 2;
        uint32_t bro  = (uint32_t)(((lane & 7) + (lane >> 4) * 8) * LQ) * 2;
        uint32_t bco2 = (uint32_t)(((lane >> 3) & 1) * 8) * 2;
#pragma unroll
        for (int ck = 0; ck < 4; ck++) {
            uint32_t kb = (uint32_t)(ck * 16) * 2;
            uint32_t aqh[4], aql[4];
            ldsm4(aqh, sB + oQh + arow + acol + kb);
            ldsm4(aql, sB + oQl + arow + acol + kb);
#pragma unroll
            for (int pr = 0; pr < 4; pr++) {
                uint32_t ro = (uint32_t)(pr * 16 * LQ) * 2;
                uint32_t bh[4], bl[4];
                ldsm4(bh, sB + oKh + bro + ro + bco2 + kb);
                ldsm4(bl, sB + oKl + bro + ro + bco2 + kb);
#pragma unroll
                for (int hf = 0; hf < 2; hf++) {
                    int tn = pr * 2 + hf;
                    mma16816(s[tn], aqh, bh + hf * 2);
                    mma16816(s[tn], aqh, bl + hf * 2);
                    mma16816(s[tn], aql, bh + hf * 2);
                }
            }
        }

        // bias + mask + online softmax (rows grp, grp+8)
        int a = lane & 3, grp = lane >> 2;
        bool mm = (k0 + 63 > qw);
        float alpha0, alpha1;
#pragma unroll
        for (int half = 0; half < 2; half++) {
            int q = qw + grp + 8 * half;
            const uint4* bp = (const uint4*)(pk + ((size_t)b * Tt + q) * Tt + k0 + 16 * a);
            uint4 u[4] = {bp[0], bp[1], bp[2], bp[3]};
            const uint32_t* ub = (const uint32_t*)u;
            float mx = -1e30f;
#pragma unroll
            for (int nt = 0; nt < 8; nt++)
#pragma unroll
                for (int e = 0; e < 2; e++) {
                    int kk = 2 * nt + e;
                    uint32_t pv = ub[kk];
                    float sv = s[nt][half * 2 + e] + bco * __uint_as_float(pv << 16)
                               + ets[pv >> 16];
                    if (mm && (k0 + 16 * a + kk > q)) sv = -1e30f;
                    s[nt][half * 2 + e] = sv;
                    mx = fmaxf(mx, sv);
                }
            mx = fmaxf(mx, __shfl_xor_sync(0xffffffffu, mx, 1));
            mx = fmaxf(mx, __shfl_xor_sync(0xffffffffu, mx, 2));
            float mold = half ? m1r : m0r;
            float mnew = fmaxf(mold, mx);
            float sum = 0.f;
#pragma unroll
            for (int nt = 0; nt < 8; nt++)
#pragma unroll
                for (int e = 0; e < 2; e++) {
                    float p = __expf(s[nt][half * 2 + e] - mnew);
                    s[nt][half * 2 + e] = p;
                    sum += p;
                }
            sum += __shfl_xor_sync(0xffffffffu, sum, 1);
            sum += __shfl_xor_sync(0xffffffffu, sum, 2);
            float al = __expf(mold - mnew);
            if (half == 0) { m0r = mnew; l0r = l0r * al + sum; alpha0 = al; }
            else           { m1r = mnew; l1r = l1r * al + sum; alpha1 = al; }
        }

        // O = O*alpha + P V
#pragma unroll
        for (int nt = 0; nt < 8; nt++) {
            o[nt][0] *= alpha0; o[nt][1] *= alpha0;
            o[nt][2] *= alpha1; o[nt][3] *= alpha1;
        }
#pragma unroll
        for (int j = 0; j < 4; j++) {
            uint32_t ah[4], al2[4];
            pk2(s[2*j][0],   s[2*j][1],   ah[0], al2[0]);
            pk2(s[2*j][2],   s[2*j][3],   ah[1], al2[1]);
            pk2(s[2*j+1][0], s[2*j+1][1], ah[2], al2[2]);
            pk2(s[2*j+1][2], s[2*j+1][3], ah[3], al2[3]);
            uint32_t kb = (uint32_t)(j * 16) * 2;
#pragma unroll
            for (int pr = 0; pr < 4; pr++) {
                uint32_t ro = (uint32_t)(pr * 16 * LQ) * 2;
                uint32_t vh[4], vl[4];
                ldsm4(vh, sB + oVh + bro + ro + bco2 + kb);
                ldsm4(vl, sB + oVl + bro + ro + bco2 + kb);
#pragma unroll
                for (int hf = 0; hf < 2; hf++) {
                    int tn = pr * 2 + hf;
                    mma16816(o[tn], ah, vh + hf * 2);
                    mma16816(o[tn], ah, vl + hf * 2);
                    mma16816(o[tn], al2, vh + hf * 2);
                }
            }
        }
    }

    // finalize
    float il0 = 1.f / l0r, il1 = 1.f / l1r;
    int grp = lane >> 2;
    float* ao = g_ao + ((size_t)b * Tt + qw + grp) * Dd + h * 64 + (lane & 3) * 2;
#pragma unroll
    for (int nt = 0; nt < 8; nt++) {
        *(float2*)(ao + nt * 8)          = make_float2(o[nt][0] * il0, o[nt][1] * il0);
        *(float2*)(ao + 8 * Dd + nt * 8) = make_float2(o[nt][2] * il1, o[nt][3] * il1);
    }
}

// ---------------------------------------------------------------------------
extern "C" void kernel_launch(void* const* d_in, const int* in_sizes, int n_in,
                              void* d_out, int out_size) {
    const float* x     = (const float*)d_in[0];
    const float* gadj  = (const float*)d_in[1];
    const int*   etyp  = (const int*)d_in[2];
    const float* wqkv  = (const float*)d_in[3];
    const float* wproj = (const float*)d_in[4];
    const float* abias = (const float*)d_in[5];
    const float* etab  = (const float*)d_in[6];
    float* out = (float*)d_out;

    __nv_bfloat16 *xhi, *xlo, *wqhi, *wqlo, *wphi, *wplo, *aohi, *aolo;
    uint32_t* packp; float* ao;
    cudaGetSymbolAddress((void**)&xhi,  g_xhi);   cudaGetSymbolAddress((void**)&xlo,  g_xlo);
    cudaGetSymbolAddress((void**)&wqhi, g_wqThi); cudaGetSymbolAddress((void**)&wqlo, g_wqTlo);
    cudaGetSymbolAddress((void**)&wphi, g_wpThi); cudaGetSymbolAddress((void**)&wplo, g_wpTlo);
    cudaGetSymbolAddress((void**)&aohi, g_aohi);  cudaGetSymbolAddress((void**)&aolo, g_aolo);
    cudaGetSymbolAddress((void**)&packp, g_pack); cudaGetSymbolAddress((void**)&ao, g_ao);

    const int SHM = 2 * BUF_B;
    cudaFuncSetAttribute(mma_gemm, cudaFuncAttributeMaxDynamicSharedMemorySize, SHM);
    const int SMA = (128 * LQ * 2 + 64 * LQ * 4) * 2 + 128;
    cudaFuncSetAttribute(attn_mma, cudaFuncAttributeMaxDynamicSharedMemorySize, SMA);

    split_kernel<<<(Bb * Tt * Dd) / 1024, 256>>>(x, xhi, xlo);
    transsplit<<<dim3(3 * Dd / 32, Dd / 32), dim3(32, 8)>>>(wqkv, wqhi, wqlo, Dd, 3 * Dd);
    transsplit<<<dim3(Dd / 32, Dd / 32), dim3(32, 8)>>>(wproj, wphi, wplo, Dd, Dd);
    pack_bias<<<(int)(((size_t)Bb * Tt * Tt) / 1024), 256>>>(gadj, etyp, packp);

    mma_gemm<<<dim3(3 * Dd / 128, Bb * Tt / 128), 256, SHM>>>(
        xhi, xlo, wqhi, wqlo, 3 * Dd, nullptr, 1);

    attn_mma<<<dim3(Tt / 128, Hh, Bb), 256, SMA>>>(packp, abias, etab);

    split_kernel<<<(Bb * Tt * Dd) / 1024, 256>>>(ao, aohi, aolo);
    mma_gemm<<<dim3(Dd / 128, Bb * Tt / 128), 256, SHM>>>(
        aohi, aolo, wphi, wplo, Dd, out, 0);
}